// round 1
// baseline (speedup 1.0000x reference)
#include <cuda_runtime.h>
#include <math.h>

#define NE     200000
#define NI     100000
#define NRELM1 39
#define DIM    64
#define NEDGE  1500000
#define KEDGE  256
#define KITEM  100
// 1 / (2 * sqrt(32)) : per-head 1/sqrt(Dk), then mean over 2 heads
#define SCALE  0.08838834764831845f

#define CAND_MAX 2048

// ---------------- scratch (static __device__, no allocations) ----------------
__device__ float    g_proj[NE * DIM];      // entity_emb @ W_Q
__device__ float    g_logits[NEDGE];
__device__ float    g_ex[NEDGE];
__device__ float    g_noisy[NEDGE];
__device__ unsigned g_segmax[NE];          // float mapped to ordered uint
__device__ float    g_dd[2 * NE];          // [denom, deg] interleaved
__device__ float    g_sumnode[NE];

struct RSCtl { unsigned prefix; int shift; unsigned kth; int kRem; int cnt; };
__device__ RSCtl    g_ctl;
__device__ unsigned g_hist[256];
__device__ unsigned long long g_cand[CAND_MAX];

// ---------------- float <-> order-preserving uint ----------------
__device__ __forceinline__ unsigned fkey(float f) {
    unsigned u = __float_as_uint(f);
    return (u & 0x80000000u) ? ~u : (u | 0x80000000u);
}
__device__ __forceinline__ float keyf(unsigned k) {
    unsigned u = (k & 0x80000000u) ? (k & 0x7FFFFFFFu) : ~k;
    return __uint_as_float(u);
}

// ---------------- 1) projection: proj = emb @ W_Q (64x64 tile, 8x4 regs) ----
__global__ void k_proj(const float* __restrict__ emb, const float* __restrict__ W) {
    __shared__ float sE[64 * 64];
    __shared__ float sW[64 * 64];
    int tid = threadIdx.x;               // 128 threads
    int base = blockIdx.x * 64 * DIM;    // 64 rows per block, NE = 3125*64 exactly

    const float4* ev = (const float4*)(emb + base);
    const float4* wv = (const float4*)W;
    float4* sev = (float4*)sE;
    float4* swv = (float4*)sW;
    #pragma unroll
    for (int i = tid; i < 1024; i += 128) { sev[i] = ev[i]; swv[i] = wv[i]; }
    __syncthreads();

    int tr = tid >> 4;   // 0..7  -> rows tr*8 .. tr*8+7
    int tc = tid & 15;   // cols tc*4 .. tc*4+3

    float acc[8][4];
    #pragma unroll
    for (int i = 0; i < 8; i++)
        #pragma unroll
        for (int j = 0; j < 4; j++) acc[i][j] = 0.0f;

    #pragma unroll 8
    for (int d = 0; d < 64; d++) {
        float4 w = *(const float4*)&sW[d * 64 + tc * 4];
        #pragma unroll
        for (int i = 0; i < 8; i++) {
            float e = sE[(tr * 8 + i) * 64 + d];
            acc[i][0] += e * w.x; acc[i][1] += e * w.y;
            acc[i][2] += e * w.z; acc[i][3] += e * w.w;
        }
    }
    #pragma unroll
    for (int i = 0; i < 8; i++) {
        *(float4*)&g_proj[base + (tr * 8 + i) * 64 + tc * 4] =
            make_float4(acc[i][0], acc[i][1], acc[i][2], acc[i][3]);
    }
}

// ---------------- 2) zero node accumulators ----------------
__global__ void k_init() {
    int i = blockIdx.x * blockDim.x + threadIdx.x;
    if (i < NE) {
        g_segmax[i] = 0u;            // key of most-negative float
        g_dd[2 * i] = 0.0f;          // denom
        g_dd[2 * i + 1] = 0.0f;      // deg
        g_sumnode[i] = 0.0f;
    }
}

// ---------------- 3) per-edge logits + scatter (max/deg/sum) ----------------
__global__ void k_edge(const int* __restrict__ head, const int* __restrict__ tail,
                       const int* __restrict__ etype, const float* __restrict__ rel) {
    int e = blockIdx.x * blockDim.x + threadIdx.x;
    if (e >= NEDGE) return;
    int h = head[e], t = tail[e], r = etype[e] - 1;

    const float4* q  = (const float4*)&g_proj[h * DIM];
    const float4* k  = (const float4*)&g_proj[t * DIM];
    const float4* rr = (const float4*)&rel[r * DIM];

    float acc = 0.0f;
    #pragma unroll
    for (int i = 0; i < 16; i++) {
        float4 a = __ldg(&q[i]);
        float4 b = __ldg(&k[i]);
        float4 c = __ldg(&rr[i]);
        acc += a.x * b.x * c.x + a.y * b.y * c.y + a.z * b.z * c.z + a.w * b.w * c.w;
    }
    float lg = acc * SCALE;
    g_logits[e] = lg;
    atomicMax(&g_segmax[h], fkey(lg));
    atomicAdd(&g_dd[2 * h + 1], 1.0f);
    atomicAdd(&g_sumnode[h], lg);
    atomicAdd(&g_sumnode[t], lg);
}

// ---------------- 4) ex = exp(logit - max); denom scatter ----------------
__global__ void k_expdenom(const int* __restrict__ head) {
    int e = blockIdx.x * blockDim.x + threadIdx.x;
    if (e >= NEDGE) return;
    int h = head[e];
    float m = keyf(g_segmax[h]);
    float ex = expf(g_logits[e] - m);
    g_ex[e] = ex;
    atomicAdd(&g_dd[2 * h], ex);
}

// ---------------- 5) score = ex/denom*deg; noisy = score + gumbel ------------
__global__ void k_score(const int* __restrict__ head, const float* __restrict__ noise,
                        float* __restrict__ out) {
    int e = blockIdx.x * blockDim.x + threadIdx.x;
    if (e >= NEDGE) return;
    int h = head[e];
    float2 dd = *(const float2*)&g_dd[2 * h];   // (denom, deg)
    float sc = g_ex[e] * dd.y / dd.x;
    out[e] = sc;
    float u = noise[e];
    g_noisy[e] = sc - logf(-logf(u));
}

// ---------------- top-K via 4-pass radix select ----------------
__device__ __forceinline__ const float* rs_data(int which) {
    return which ? g_sumnode : g_noisy;
}

__global__ void k_rs_init(int K) {
    int t = threadIdx.x;
    g_hist[t] = 0u;
    if (t == 0) { g_ctl.prefix = 0u; g_ctl.shift = 24; g_ctl.kth = 0u; g_ctl.kRem = K; g_ctl.cnt = 0; }
}

__global__ void k_rs_hist(int which, int n) {
    __shared__ unsigned sh[256];
    sh[threadIdx.x] = 0u;
    __syncthreads();
    const float* d = rs_data(which);
    int shift = g_ctl.shift;
    unsigned prefix = g_ctl.prefix;
    unsigned mask = (shift == 24) ? 0u : (0xFFFFFFFFu << (shift + 8));
    for (int i = blockIdx.x * blockDim.x + threadIdx.x; i < n; i += gridDim.x * blockDim.x) {
        unsigned key = fkey(d[i]);
        if ((key & mask) == prefix)
            atomicAdd(&sh[(key >> shift) & 255u], 1u);
    }
    __syncthreads();
    unsigned c = sh[threadIdx.x];
    if (c) atomicAdd(&g_hist[threadIdx.x], c);
}

__global__ void k_rs_scan() {
    if (threadIdx.x == 0) {
        int kRem = g_ctl.kRem;
        unsigned cum = 0;
        int sel = 0;
        for (int b = 255; b >= 0; --b) {
            unsigned c = g_hist[b];
            if (cum + c >= (unsigned)kRem) { sel = b; break; }
            cum += c;
        }
        g_ctl.kRem = kRem - (int)cum;
        g_ctl.prefix |= ((unsigned)sel) << g_ctl.shift;
        if (g_ctl.shift == 0) g_ctl.kth = g_ctl.prefix;
        g_ctl.shift -= 8;
    }
    __syncthreads();
    g_hist[threadIdx.x] = 0u;
}

__global__ void k_rs_collect(int which, int n) {
    const float* d = rs_data(which);
    unsigned kth = g_ctl.kth;
    for (int i = blockIdx.x * blockDim.x + threadIdx.x; i < n; i += gridDim.x * blockDim.x) {
        unsigned key = fkey(d[i]);
        if (key >= kth) {
            int p = atomicAdd(&g_ctl.cnt, 1);
            if (p < CAND_MAX)
                g_cand[p] = (((unsigned long long)(~key)) << 32) | (unsigned)i;
        }
    }
}

// one-block bitonic sort of candidates: ascending on (~key<<32 | idx)
// == descending by value, ascending by index (jax top_k tie-break)
__global__ void k_rs_sortout(float* __restrict__ outV, float* __restrict__ outI, int K) {
    __shared__ unsigned long long s[CAND_MAX];
    int cnt = g_ctl.cnt;
    if (cnt > CAND_MAX) cnt = CAND_MAX;
    for (int i = threadIdx.x; i < CAND_MAX; i += blockDim.x)
        s[i] = (i < cnt) ? g_cand[i] : 0xFFFFFFFFFFFFFFFFull;
    __syncthreads();
    for (int k = 2; k <= CAND_MAX; k <<= 1) {
        for (int j = k >> 1; j > 0; j >>= 1) {
            for (int i = threadIdx.x; i < CAND_MAX; i += blockDim.x) {
                int p = i ^ j;
                if (p > i) {
                    bool up = ((i & k) == 0);
                    unsigned long long a = s[i], b = s[p];
                    if ((a > b) == up) { s[i] = b; s[p] = a; }
                }
            }
            __syncthreads();
        }
    }
    if (threadIdx.x < K) {
        unsigned long long c = s[threadIdx.x];
        unsigned key = ~(unsigned)(c >> 32);
        outV[threadIdx.x] = keyf(key);
        outI[threadIdx.x] = (float)(unsigned)(c & 0xFFFFFFFFu);
    }
}

// ---------------- host-side orchestration ----------------
static void run_topk(int which, int n, int K, float* outV, float* outI) {
    int grid = (n + 255) / 256;
    if (grid > 1024) grid = 1024;
    k_rs_init<<<1, 256>>>(K);
    for (int p = 0; p < 4; p++) {
        k_rs_hist<<<grid, 256>>>(which, n);
        k_rs_scan<<<1, 256>>>();
    }
    k_rs_collect<<<grid, 256>>>(which, n);
    k_rs_sortout<<<1, 1024>>>(outV, outI, K);
}

extern "C" void kernel_launch(void* const* d_in, const int* in_sizes, int n_in,
                              void* d_out, int out_size) {
    const float* emb   = (const float*)d_in[0];   // [NE, 64]
    const float* WQ    = (const float*)d_in[1];   // [64, 64]
    const float* rel   = (const float*)d_in[2];   // [39, 64]
    const float* noise = (const float*)d_in[3];   // [NEDGE]
    const int*   eidx  = (const int*)d_in[4];     // [2, NEDGE]
    const int*   etype = (const int*)d_in[5];     // [NEDGE]
    const int* head = eidx;
    const int* tail = eidx + NEDGE;
    float* out = (float*)d_out;

    // output layout (all float32):
    // [0, E)            edge_attn_score
    // [E, E+256)        topk_v   (noisy)
    // [E+256, E+512)    topk edge ids (as float)
    // [E+512, E+612)    top_items_v
    // [E+612, E+712)    top item ids (as float)
    float* out_tkv = out + NEDGE;
    float* out_tki = out + NEDGE + KEDGE;
    float* out_itv = out + NEDGE + 2 * KEDGE;
    float* out_iti = out + NEDGE + 2 * KEDGE + KITEM;

    k_proj<<<NE / 64, 128>>>(emb, WQ);
    k_init<<<(NE + 255) / 256, 256>>>();
    k_edge<<<(NEDGE + 255) / 256, 256>>>(head, tail, etype, rel);
    k_expdenom<<<(NEDGE + 255) / 256, 256>>>(head);
    k_score<<<(NEDGE + 255) / 256, 256>>>(head, noise, out);

    run_topk(/*which=*/0, NEDGE, KEDGE, out_tkv, out_tki);   // gumbel-noisy edge topk
    run_topk(/*which=*/1, NI,    KITEM, out_itv, out_iti);   // item logit-sum topk
}

// round 2
// speedup vs baseline: 1.1438x; 1.1438x over previous
#include <cuda_runtime.h>
#include <math.h>

#define NE     200000
#define NI     100000
#define DIM    64
#define NEDGE  1500000
#define KEDGE  256
#define KITEM  100
// 1 / (2 * sqrt(32)) : per-head 1/sqrt(Dk), then mean over 2 heads
#define SCALE  0.08838834764831845f

#define CAND_MAX 1024

// ---------------- scratch (static __device__, no allocations) ----------------
__device__ float    g_proj[NE * DIM];      // entity_emb @ W_Q
__device__ float    g_ex[NEDGE];           // exp(logit)  (no max-shift needed; |logit| tiny)
__device__ float    g_noisy[NEDGE];
__device__ float    g_dd[2 * NE];          // [denom, deg] interleaved
__device__ float    g_sumnode[NE];

struct RSCtl { unsigned prefix; int shift; unsigned kth; int kRem; int cnt; };
__device__ RSCtl    g_ctl[2];              // 0 = edge topk, 1 = item topk
__device__ unsigned g_hist[2][256];
__device__ unsigned long long g_cand[2][CAND_MAX];
__device__ unsigned g_arrive;              // last-block-done counter (reset by last block)

// ---------------- float <-> order-preserving uint ----------------
__device__ __forceinline__ unsigned fkey(float f) {
    unsigned u = __float_as_uint(f);
    return (u & 0x80000000u) ? ~u : (u | 0x80000000u);
}
__device__ __forceinline__ float keyf(unsigned k) {
    unsigned u = (k & 0x80000000u) ? (k & 0x7FFFFFFFu) : ~k;
    return __uint_as_float(u);
}

// ---------------- last-block-done ----------------
__device__ __forceinline__ bool last_block_arrive() {
    __threadfence();
    __shared__ bool s_last;
    if (threadIdx.x == 0) {
        unsigned v = atomicAdd(&g_arrive, 1u);
        s_last = (v == gridDim.x - 1);
        if (s_last) g_arrive = 0u;   // all blocks arrived; safe to reset for next kernel
    }
    __syncthreads();
    return s_last;
}

// ---------------- parallel radix-select step: pick bin, update ctl ----------
// executed by ONE block with >=256 threads; also zeroes g_hist for next pass
__device__ void scan_select(int which) {
    __shared__ unsigned sc[256];
    __shared__ unsigned ssum[256];
    int t = threadIdx.x;
    if (t < 256) {
        unsigned c = g_hist[which][t];
        g_hist[which][t] = 0u;
        sc[t] = c;
        ssum[t] = c;
    }
    __syncthreads();
    // suffix inclusive sum: ssum[t] = sum_{b >= t} count[b]
    #pragma unroll
    for (int off = 1; off < 256; off <<= 1) {
        unsigned v = 0;
        if (t < 256) { v = ssum[t]; if (t + off < 256) v += ssum[t + off]; }
        __syncthreads();
        if (t < 256) ssum[t] = v;
        __syncthreads();
    }
    if (t < 256) {
        int kRem = g_ctl[which].kRem;
        unsigned incl = ssum[t];
        unsigned excl = incl - sc[t];
        if ((int)excl < kRem && kRem <= (int)incl) {   // exactly one t satisfies this
            int shift = g_ctl[which].shift;
            g_ctl[which].kRem  = kRem - (int)excl;
            unsigned pre = g_ctl[which].prefix | ((unsigned)t << shift);
            g_ctl[which].prefix = pre;
            g_ctl[which].shift  = shift - 8;
            if (shift == 0) g_ctl[which].kth = pre;
        }
    }
}

// ---------------- 1) projection (+ fused global init) ----------------
__global__ void k_proj(const float* __restrict__ emb, const float* __restrict__ W) {
    __shared__ float sE[64 * 64];
    __shared__ float sW[64 * 64];
    int tid = threadIdx.x;               // 128 threads
    int base = blockIdx.x * 64 * DIM;    // 64 rows per block, NE = 3125*64 exactly
    int eb = blockIdx.x * 64;

    // fused init: per-node accumulators for this block's 64 entities
    g_dd[2 * eb + tid] = 0.0f;           // 128 floats = denom+deg for 64 entities
    if (tid < 64) g_sumnode[eb + tid] = 0.0f;
    if (blockIdx.x == 0) {
        #pragma unroll
        for (int i = tid; i < 256; i += 128) { g_hist[0][i] = 0u; g_hist[1][i] = 0u; }
        if (tid == 0) {
            g_ctl[0].prefix = 0u; g_ctl[0].shift = 24; g_ctl[0].kth = 0u;
            g_ctl[0].kRem = KEDGE; g_ctl[0].cnt = 0;
            g_ctl[1].prefix = 0u; g_ctl[1].shift = 24; g_ctl[1].kth = 0u;
            g_ctl[1].kRem = KITEM; g_ctl[1].cnt = 0;
            g_arrive = 0u;
        }
    }

    const float4* ev = (const float4*)(emb + base);
    const float4* wv = (const float4*)W;
    float4* sev = (float4*)sE;
    float4* swv = (float4*)sW;
    #pragma unroll
    for (int i = tid; i < 1024; i += 128) { sev[i] = ev[i]; swv[i] = wv[i]; }
    __syncthreads();

    int tr = tid >> 4;   // 0..7  -> rows tr*8 .. tr*8+7
    int tc = tid & 15;   // cols tc*4 .. tc*4+3

    float acc[8][4];
    #pragma unroll
    for (int i = 0; i < 8; i++)
        #pragma unroll
        for (int j = 0; j < 4; j++) acc[i][j] = 0.0f;

    #pragma unroll 8
    for (int d = 0; d < 64; d++) {
        float4 w = *(const float4*)&sW[d * 64 + tc * 4];
        #pragma unroll
        for (int i = 0; i < 8; i++) {
            float e = sE[(tr * 8 + i) * 64 + d];
            acc[i][0] += e * w.x; acc[i][1] += e * w.y;
            acc[i][2] += e * w.z; acc[i][3] += e * w.w;
        }
    }
    #pragma unroll
    for (int i = 0; i < 8; i++) {
        *(float4*)&g_proj[base + (tr * 8 + i) * 64 + tc * 4] =
            make_float4(acc[i][0], acc[i][1], acc[i][2], acc[i][3]);
    }
}

// ---------------- 2) per-edge logit -> exp + scatter (denom/deg/sumnode) ----
__global__ void k_edge(const int* __restrict__ head, const int* __restrict__ tail,
                       const int* __restrict__ etype, const float* __restrict__ rel) {
    int e = blockIdx.x * blockDim.x + threadIdx.x;
    if (e >= NEDGE) return;
    int h = head[e], t = tail[e], r = etype[e] - 1;

    const float4* q  = (const float4*)&g_proj[h * DIM];
    const float4* k  = (const float4*)&g_proj[t * DIM];
    const float4* rr = (const float4*)&rel[r * DIM];

    float a0 = 0.f, a1 = 0.f, a2 = 0.f, a3 = 0.f;
    #pragma unroll
    for (int i = 0; i < 16; i++) {
        float4 a = __ldg(&q[i]);
        float4 b = __ldg(&k[i]);
        float4 c = __ldg(&rr[i]);
        a0 += a.x * b.x * c.x; a1 += a.y * b.y * c.y;
        a2 += a.z * b.z * c.z; a3 += a.w * b.w * c.w;
    }
    float lg = (a0 + a1 + a2 + a3) * SCALE;
    // |lg| << 1, so softmax without max-subtraction is numerically exact here
    float ex = expf(lg);
    g_ex[e] = ex;
    atomicAdd(&g_dd[2 * h], ex);          // denom
    atomicAdd(&g_dd[2 * h + 1], 1.0f);    // deg
    atomicAdd(&g_sumnode[h], lg);
    atomicAdd(&g_sumnode[t], lg);
}

// ---------------- 3) score + gumbel + fused edge-topk pass-1 hist+scan -------
__global__ void k_score(const int* __restrict__ head, const float* __restrict__ noise,
                        float* __restrict__ out) {
    __shared__ unsigned sh[256];
    sh[threadIdx.x] = 0u;
    __syncthreads();
    int base = blockIdx.x * (256 * 4) + threadIdx.x;
    #pragma unroll
    for (int j = 0; j < 4; j++) {
        int e = base + j * 256;
        if (e < NEDGE) {
            int h = head[e];
            float2 dd = *(const float2*)&g_dd[2 * h];   // (denom, deg)
            float sc = g_ex[e] * dd.y / dd.x;
            out[e] = sc;
            float ns = sc - logf(-logf(noise[e]));
            g_noisy[e] = ns;
            atomicAdd(&sh[fkey(ns) >> 24], 1u);
        }
    }
    __syncthreads();
    unsigned c = sh[threadIdx.x];
    if (c) atomicAdd(&g_hist[0][threadIdx.x], c);
    if (last_block_arrive()) scan_select(0);
}

// ---------------- 4) radix-select histogram pass (with fused scan) -----------
__global__ void k_hist(int which) {
    const float* d = which ? g_sumnode : g_noisy;
    int n = which ? NI : NEDGE;
    __shared__ unsigned sh[256];
    sh[threadIdx.x] = 0u;
    int shift = g_ctl[which].shift;
    unsigned prefix = g_ctl[which].prefix;
    unsigned mask = (shift == 24) ? 0u : (0xFFFFFFFFu << (shift + 8));
    __syncthreads();
    for (int i = blockIdx.x * blockDim.x + threadIdx.x; i < n; i += gridDim.x * blockDim.x) {
        unsigned key = fkey(d[i]);
        if ((key & mask) == prefix)
            atomicAdd(&sh[(key >> shift) & 255u], 1u);
    }
    __syncthreads();
    unsigned c = sh[threadIdx.x];
    if (c) atomicAdd(&g_hist[which][c ? threadIdx.x : threadIdx.x], c);
    if (last_block_arrive()) scan_select(which);
}

// ---------------- 5) collect >= kth, last block sorts & writes outputs -------
// key packing (~key<<32 | idx) ascending == value desc, idx asc (jax tie-break)
__global__ void k_collect(int which, float* __restrict__ outV, float* __restrict__ outI,
                          int K) {
    const float* d = which ? g_sumnode : g_noisy;
    int n = which ? NI : NEDGE;
    unsigned kth = g_ctl[which].kth;
    for (int i = blockIdx.x * blockDim.x + threadIdx.x; i < n; i += gridDim.x * blockDim.x) {
        unsigned key = fkey(d[i]);
        if (key >= kth) {
            int p = atomicAdd(&g_ctl[which].cnt, 1);
            if (p < CAND_MAX)
                g_cand[which][p] = (((unsigned long long)(~key)) << 32) | (unsigned)i;
        }
    }
    if (last_block_arrive()) {
        __shared__ unsigned long long s[CAND_MAX];
        int cnt = g_ctl[which].cnt;
        if (cnt > CAND_MAX) cnt = CAND_MAX;
        for (int i = threadIdx.x; i < CAND_MAX; i += blockDim.x)
            s[i] = (i < cnt) ? g_cand[which][i] : 0xFFFFFFFFFFFFFFFFull;
        __syncthreads();
        for (int k = 2; k <= CAND_MAX; k <<= 1) {
            for (int j = k >> 1; j > 0; j >>= 1) {
                for (int i = threadIdx.x; i < CAND_MAX; i += blockDim.x) {
                    int p = i ^ j;
                    if (p > i) {
                        bool up = ((i & k) == 0);
                        unsigned long long a = s[i], b = s[p];
                        if ((a > b) == up) { s[i] = b; s[p] = a; }
                    }
                }
                __syncthreads();
            }
        }
        for (int t = threadIdx.x; t < K; t += blockDim.x) {
            unsigned long long cc = s[t];
            unsigned key = ~(unsigned)(cc >> 32);
            outV[t] = keyf(key);
            outI[t] = (float)(unsigned)(cc & 0xFFFFFFFFu);
        }
    }
}

// ---------------- host-side orchestration ----------------
extern "C" void kernel_launch(void* const* d_in, const int* in_sizes, int n_in,
                              void* d_out, int out_size) {
    const float* emb   = (const float*)d_in[0];   // [NE, 64]
    const float* WQ    = (const float*)d_in[1];   // [64, 64]
    const float* rel   = (const float*)d_in[2];   // [39, 64]
    const float* noise = (const float*)d_in[3];   // [NEDGE]
    const int*   eidx  = (const int*)d_in[4];     // [2, NEDGE]
    const int*   etype = (const int*)d_in[5];     // [NEDGE]
    const int* head = eidx;
    const int* tail = eidx + NEDGE;
    float* out = (float*)d_out;

    // output layout (all float32):
    // [0, E) edge_attn_score | [E, E+256) topk_v | [E+256, E+512) topk edge ids
    // [E+512, E+612) top_items_v | [E+612, E+712) top item ids
    float* out_tkv = out + NEDGE;
    float* out_tki = out + NEDGE + KEDGE;
    float* out_itv = out + NEDGE + 2 * KEDGE;
    float* out_iti = out + NEDGE + 2 * KEDGE + KITEM;

    k_proj<<<NE / 64, 128>>>(emb, WQ);
    k_edge<<<(NEDGE + 255) / 256, 256>>>(head, tail, etype, rel);
    k_score<<<(NEDGE + 1023) / 1024, 256>>>(head, noise, out);   // + edge hist pass 1

    // edge topk: passes 2-4 then collect+sort
    k_hist<<<1024, 256>>>(0);
    k_hist<<<1024, 256>>>(0);
    k_hist<<<1024, 256>>>(0);
    k_collect<<<256, 1024>>>(0, out_tkv, out_tki, KEDGE);

    // item topk: passes 1-4 then collect+sort
    k_hist<<<391, 256>>>(1);
    k_hist<<<391, 256>>>(1);
    k_hist<<<391, 256>>>(1);
    k_hist<<<391, 256>>>(1);
    k_collect<<<98, 1024>>>(1, out_itv, out_iti, KITEM);
}

// round 3
// speedup vs baseline: 1.3103x; 1.1455x over previous
#include <cuda_runtime.h>
#include <math.h>

#define NE     200000
#define NI     100000
#define DIM    64
#define NEDGE  1500000
#define KEDGE  256
#define KITEM  100
// 1 / (2 * sqrt(32)) : per-head 1/sqrt(Dk), then mean over 2 heads
#define SCALE  0.08838834764831845f

#define CAND_MAX 512

// topk-edge persistent grid: 148 SM x 4 blocks, 256 thr, 10 items/thread
#define TE_BLOCKS 592
#define TE_STRIDE (TE_BLOCKS * 256)
#define TE_ITEMS  10            // 10 * 151552 = 1,515,520 >= NEDGE
// topk-item persistent grid
#define TI_BLOCKS 148
#define TI_STRIDE (TI_BLOCKS * 256)
#define TI_ITEMS  3             // 3 * 37,888 = 113,664 >= NI

// ---------------- scratch ----------------
__device__ float    g_proj[NE * DIM];
__device__ float    g_ex[NEDGE];
__device__ float    g_dd[2 * NE];          // [denom, deg] interleaved
__device__ float    g_sumnode[NE];

struct RSCtl { unsigned prefix; int shift; unsigned kth; int kRem; int cnt; };
__device__ RSCtl    g_ctl[2];
__device__ unsigned g_hist[2][256];
__device__ unsigned long long g_cand[2][CAND_MAX];

// software grid barrier state (self-resetting; gen wraps harmlessly)
__device__ unsigned g_bar_cnt;
__device__ volatile unsigned g_bar_gen;

// ---------------- helpers ----------------
__device__ __forceinline__ unsigned fkey(float f) {
    unsigned u = __float_as_uint(f);
    return (u & 0x80000000u) ? ~u : (u | 0x80000000u);
}
__device__ __forceinline__ float keyf(unsigned k) {
    unsigned u = (k & 0x80000000u) ? (k & 0x7FFFFFFFu) : ~k;
    return __uint_as_float(u);
}

// all threads fence their own global writes, then block reps rendezvous
__device__ __forceinline__ void grid_sync() {
    __threadfence();
    __syncthreads();
    if (threadIdx.x == 0) {
        unsigned gen = g_bar_gen;
        if (atomicAdd(&g_bar_cnt, 1u) == gridDim.x - 1) {
            g_bar_cnt = 0u;
            __threadfence();
            g_bar_gen = gen + 1u;
        } else {
            while (g_bar_gen == gen) { __nanosleep(64); }
        }
        __threadfence();
    }
    __syncthreads();
}

// one block (256 threads) picks the radix bin containing the kth element,
// updates ctl, zeroes hist for the next pass. volatile reads: hist bins were
// updated by other SMs via L2 atomics after our L1 may have cached them.
__device__ void scan_select(int which) {
    __shared__ unsigned s_c[256];
    __shared__ unsigned s_sum[256];
    int t = threadIdx.x;
    unsigned c = ((volatile unsigned*)g_hist[which])[t];
    g_hist[which][t] = 0u;
    s_c[t] = c;
    s_sum[t] = c;
    __syncthreads();
    #pragma unroll
    for (int off = 1; off < 256; off <<= 1) {
        unsigned v = s_sum[t];
        if (t + off < 256) v += s_sum[t + off];
        __syncthreads();
        s_sum[t] = v;
        __syncthreads();
    }
    int kRem = g_ctl[which].kRem;          // only ever touched by this block
    unsigned incl = s_sum[t];
    unsigned excl = incl - s_c[t];
    if ((int)excl < kRem && kRem <= (int)incl) {   // exactly one t
        int shift = g_ctl[which].shift;
        g_ctl[which].kRem  = kRem - (int)excl;
        unsigned pre = g_ctl[which].prefix | ((unsigned)t << shift);
        g_ctl[which].prefix = pre;
        g_ctl[which].shift  = shift - 8;
        if (shift == 0) g_ctl[which].kth = pre;
    }
}

// bitonic sort CAND_MAX elems in smem (256 threads), write top-K
__device__ void sort_and_emit(int which, float* __restrict__ outV,
                              float* __restrict__ outI, int K) {
    __shared__ unsigned long long s[CAND_MAX];
    int cnt = g_ctl[which].cnt;
    if (cnt > CAND_MAX) cnt = CAND_MAX;
    for (int i = threadIdx.x; i < CAND_MAX; i += blockDim.x)
        s[i] = (i < cnt) ? ((volatile unsigned long long*)g_cand[which])[i]
                         : 0xFFFFFFFFFFFFFFFFull;
    __syncthreads();
    for (int k = 2; k <= CAND_MAX; k <<= 1) {
        for (int j = k >> 1; j > 0; j >>= 1) {
            for (int i = threadIdx.x; i < CAND_MAX; i += blockDim.x) {
                int p = i ^ j;
                if (p > i) {
                    bool up = ((i & k) == 0);
                    unsigned long long a = s[i], b = s[p];
                    if ((a > b) == up) { s[i] = b; s[p] = a; }
                }
            }
            __syncthreads();
        }
    }
    for (int t = threadIdx.x; t < K; t += blockDim.x) {
        unsigned long long cc = s[t];
        unsigned key = ~(unsigned)(cc >> 32);
        outV[t] = keyf(key);
        outI[t] = (float)(unsigned)(cc & 0xFFFFFFFFu);
    }
}

// ---------------- 1) projection (+ fused init) ----------------
__global__ void k_proj(const float* __restrict__ emb, const float* __restrict__ W) {
    __shared__ float sE[64 * 64];
    __shared__ float sW[64 * 64];
    int tid = threadIdx.x;               // 128
    int base = blockIdx.x * 64 * DIM;
    int eb = blockIdx.x * 64;

    g_dd[2 * eb + tid] = 0.0f;
    if (tid < 64) g_sumnode[eb + tid] = 0.0f;
    if (blockIdx.x == 0) {
        #pragma unroll
        for (int i = tid; i < 256; i += 128) { g_hist[0][i] = 0u; g_hist[1][i] = 0u; }
        if (tid == 0) {
            g_ctl[0].prefix = 0u; g_ctl[0].shift = 24; g_ctl[0].kth = 0u;
            g_ctl[0].kRem = KEDGE; g_ctl[0].cnt = 0;
            g_ctl[1].prefix = 0u; g_ctl[1].shift = 24; g_ctl[1].kth = 0u;
            g_ctl[1].kRem = KITEM; g_ctl[1].cnt = 0;
        }
    }

    const float4* ev = (const float4*)(emb + base);
    const float4* wv = (const float4*)W;
    float4* sev = (float4*)sE;
    float4* swv = (float4*)sW;
    #pragma unroll
    for (int i = tid; i < 1024; i += 128) { sev[i] = ev[i]; swv[i] = wv[i]; }
    __syncthreads();

    int tr = tid >> 4;
    int tc = tid & 15;
    float acc[8][4];
    #pragma unroll
    for (int i = 0; i < 8; i++)
        #pragma unroll
        for (int j = 0; j < 4; j++) acc[i][j] = 0.0f;

    #pragma unroll 8
    for (int d = 0; d < 64; d++) {
        float4 w = *(const float4*)&sW[d * 64 + tc * 4];
        #pragma unroll
        for (int i = 0; i < 8; i++) {
            float e = sE[(tr * 8 + i) * 64 + d];
            acc[i][0] += e * w.x; acc[i][1] += e * w.y;
            acc[i][2] += e * w.z; acc[i][3] += e * w.w;
        }
    }
    #pragma unroll
    for (int i = 0; i < 8; i++)
        *(float4*)&g_proj[base + (tr * 8 + i) * 64 + tc * 4] =
            make_float4(acc[i][0], acc[i][1], acc[i][2], acc[i][3]);
}

// ---------------- 2) warp-cooperative per-edge: 16 lanes per edge ----------
// Each warp handles 2 edges; each half-warp loads the full 256B q row and
// 256B k row coalesced (4 cache lines per edge vs 32 for thread-per-edge).
__global__ void k_edge(const int* __restrict__ head, const int* __restrict__ tail,
                       const int* __restrict__ etype, const float* __restrict__ rel) {
    int warp_global = (blockIdx.x * blockDim.x + threadIdx.x) >> 5;
    int lane = threadIdx.x & 31;
    int half = lane >> 4;
    int sub  = lane & 15;
    int e = warp_global * 2 + half;      // grid sized exactly: no guard needed

    int h = __ldg(&head[e]);             // broadcast within half-warp
    int t = __ldg(&tail[e]);
    int r = __ldg(&etype[e]) - 1;

    float4 q  = *(const float4*)&g_proj[((size_t)h << 6) + (sub << 2)];
    float4 kv = *(const float4*)&g_proj[((size_t)t << 6) + (sub << 2)];
    float4 rv = __ldg((const float4*)rel + ((size_t)r << 4) + sub);

    float s = q.x * kv.x * rv.x + q.y * kv.y * rv.y
            + q.z * kv.z * rv.z + q.w * kv.w * rv.w;
    s += __shfl_xor_sync(0xffffffffu, s, 8);
    s += __shfl_xor_sync(0xffffffffu, s, 4);
    s += __shfl_xor_sync(0xffffffffu, s, 2);
    s += __shfl_xor_sync(0xffffffffu, s, 1);

    float lg = s * SCALE;
    float ex = __expf(lg);

    if (sub == 0) { g_ex[e] = ex; atomicAdd(&g_dd[2 * h], ex); }
    else if (sub == 1) atomicAdd(&g_dd[2 * h + 1], 1.0f);
    else if (sub == 2) atomicAdd(&g_sumnode[h], lg);
    else if (sub == 3) atomicAdd(&g_sumnode[t], lg);
}

// ---------------- 3) fused: score + gumbel + 4-pass radix topk (edges) ------
__global__ void __launch_bounds__(256, 4)
k_topk_edge(const int* __restrict__ head, const float* __restrict__ noise,
            float* __restrict__ out, float* __restrict__ outV,
            float* __restrict__ outI) {
    __shared__ unsigned sh[256];
    unsigned key[TE_ITEMS];
    int gtid = blockIdx.x * 256 + threadIdx.x;

    // pass A: compute score/noisy, keep keys in regs, histogram top byte
    sh[threadIdx.x] = 0u;
    __syncthreads();
    #pragma unroll
    for (int i = 0; i < TE_ITEMS; i++) {
        int e = gtid + i * TE_STRIDE;
        key[i] = 0u;
        if (e < NEDGE) {
            int h = __ldg(&head[e]);
            float2 dd = *(const float2*)&g_dd[2 * h];   // (denom, deg)
            float sc = __ldg(&g_ex[e]) * dd.y / dd.x;
            out[e] = sc;
            float ns = sc - logf(-logf(__ldg(&noise[e])));
            unsigned k = fkey(ns);
            key[i] = k;
            atomicAdd(&sh[k >> 24], 1u);
        }
    }
    __syncthreads();
    { unsigned c = sh[threadIdx.x]; if (c) atomicAdd(&g_hist[0][threadIdx.x], c); }
    grid_sync();
    if (blockIdx.x == 0) scan_select(0);
    grid_sync();

    // passes 2..4: shift 16, 8, 0 (compile-time), prefix read volatile
    #pragma unroll
    for (int pass = 1; pass < 4; pass++) {
        int shift = 24 - pass * 8;
        unsigned mask = 0xFFFFFFFFu << (shift + 8);
        unsigned prefix = ((volatile RSCtl*)&g_ctl[0])->prefix;
        sh[threadIdx.x] = 0u;
        __syncthreads();
        #pragma unroll
        for (int i = 0; i < TE_ITEMS; i++) {
            unsigned k = key[i];
            if (k && (k & mask) == prefix)
                atomicAdd(&sh[(k >> shift) & 255u], 1u);
        }
        __syncthreads();
        { unsigned c = sh[threadIdx.x]; if (c) atomicAdd(&g_hist[0][threadIdx.x], c); }
        grid_sync();
        if (blockIdx.x == 0) scan_select(0);
        grid_sync();
    }

    // collect
    unsigned kth = ((volatile RSCtl*)&g_ctl[0])->kth;
    #pragma unroll
    for (int i = 0; i < TE_ITEMS; i++) {
        unsigned k = key[i];
        if (k >= kth) {
            int p = atomicAdd(&g_ctl[0].cnt, 1);
            if (p < CAND_MAX)
                g_cand[0][p] = (((unsigned long long)(~k)) << 32)
                             | (unsigned)(gtid + i * TE_STRIDE);
        }
    }
    grid_sync();
    if (blockIdx.x == 0) sort_and_emit(0, outV, outI, KEDGE);
}

// ---------------- 4) fused: 4-pass radix topk (items) ------------------------
__global__ void __launch_bounds__(256, 4)
k_topk_item(float* __restrict__ outV, float* __restrict__ outI) {
    __shared__ unsigned sh[256];
    unsigned key[TI_ITEMS];
    int gtid = blockIdx.x * 256 + threadIdx.x;

    sh[threadIdx.x] = 0u;
    __syncthreads();
    #pragma unroll
    for (int i = 0; i < TI_ITEMS; i++) {
        int e = gtid + i * TI_STRIDE;
        key[i] = 0u;
        if (e < NI) {
            unsigned k = fkey(__ldg(&g_sumnode[e]));
            key[i] = k;
            atomicAdd(&sh[k >> 24], 1u);
        }
    }
    __syncthreads();
    { unsigned c = sh[threadIdx.x]; if (c) atomicAdd(&g_hist[1][threadIdx.x], c); }
    grid_sync();
    if (blockIdx.x == 0) scan_select(1);
    grid_sync();

    #pragma unroll
    for (int pass = 1; pass < 4; pass++) {
        int shift = 24 - pass * 8;
        unsigned mask = 0xFFFFFFFFu << (shift + 8);
        unsigned prefix = ((volatile RSCtl*)&g_ctl[1])->prefix;
        sh[threadIdx.x] = 0u;
        __syncthreads();
        #pragma unroll
        for (int i = 0; i < TI_ITEMS; i++) {
            unsigned k = key[i];
            if (k && (k & mask) == prefix)
                atomicAdd(&sh[(k >> shift) & 255u], 1u);
        }
        __syncthreads();
        { unsigned c = sh[threadIdx.x]; if (c) atomicAdd(&g_hist[1][threadIdx.x], c); }
        grid_sync();
        if (blockIdx.x == 0) scan_select(1);
        grid_sync();
    }

    unsigned kth = ((volatile RSCtl*)&g_ctl[1])->kth;
    #pragma unroll
    for (int i = 0; i < TI_ITEMS; i++) {
        unsigned k = key[i];
        if (k >= kth) {
            int p = atomicAdd(&g_ctl[1].cnt, 1);
            if (p < CAND_MAX)
                g_cand[1][p] = (((unsigned long long)(~k)) << 32)
                             | (unsigned)(gtid + i * TI_STRIDE);
        }
    }
    grid_sync();
    if (blockIdx.x == 0) sort_and_emit(1, outV, outI, KITEM);
}

// ---------------- host ----------------
extern "C" void kernel_launch(void* const* d_in, const int* in_sizes, int n_in,
                              void* d_out, int out_size) {
    const float* emb   = (const float*)d_in[0];
    const float* WQ    = (const float*)d_in[1];
    const float* rel   = (const float*)d_in[2];
    const float* noise = (const float*)d_in[3];
    const int*   eidx  = (const int*)d_in[4];
    const int*   etype = (const int*)d_in[5];
    const int* head = eidx;
    const int* tail = eidx + NEDGE;
    float* out = (float*)d_out;

    float* out_tkv = out + NEDGE;
    float* out_tki = out + NEDGE + KEDGE;
    float* out_itv = out + NEDGE + 2 * KEDGE;
    float* out_iti = out + NEDGE + 2 * KEDGE + KITEM;

    k_proj<<<NE / 64, 128>>>(emb, WQ);
    k_edge<<<NEDGE / 16, 256>>>(head, tail, etype, rel);   // 2 edges/warp, 8 warps/block
    k_topk_edge<<<TE_BLOCKS, 256>>>(head, noise, out, out_tkv, out_tki);
    k_topk_item<<<TI_BLOCKS, 256>>>(out_itv, out_iti);
}